// round 6
// baseline (speedup 1.0000x reference)
#include <cuda_runtime.h>
#include <cuda_bf16.h>
#include <math.h>
#include <cstdint>

#define M_TOT 8192
#define NS    4096
#define DDIM  256
#define INV_T 14.285714285714286f   // 1 / 0.07

// sim kernel: 128x128 tile, int8 K=256 (256 B/row) in 2 chunks of 128 B.
// Whole A+B tile resident: 2 * 32 KB = 64 KB dynamic smem -> 2 CTAs/SM.
#define CHUNK_BYTES   (128 * 128)            // 16 KB: 128 rows x 128 B (K-half)
#define TILE_BYTES    (2 * CHUNK_BYTES)      // 32 KB per matrix
#define SMEM_TOTAL    (2 * TILE_BYTES)       // 64 KB (A then B)

// Scratch (allocation-free rule: __device__ globals)
__device__ __align__(16) int   g_feati[M_TOT * 64];  // int8 features, 2 MB
__device__ float g_scale[M_TOT];                     // per-row dequant scale
__device__ float g_acc[M_TOT];
__device__ float g_pos[NS];

// ---------------- helpers ----------------
__device__ __forceinline__ uint32_t smem_u32(const void* p) {
    uint32_t a;
    asm("{ .reg .u64 t; cvta.to.shared.u64 t, %1; cvt.u32.u64 %0, t; }" : "=r"(a) : "l"(p));
    return a;
}
#define CP16(dst, src) \
    asm volatile("cp.async.cg.shared.global [%0], [%1], 16;" :: "r"(dst), "l"(src))
#define CP_COMMIT() asm volatile("cp.async.commit_group;" ::: "memory")
#define CP_WAIT(n)  asm volatile("cp.async.wait_group %0;" :: "n"(n) : "memory")

#define LDSM4(r0, r1, r2, r3, addr) \
    asm volatile("ldmatrix.sync.aligned.m8n8.x4.shared.b16 {%0,%1,%2,%3}, [%4];" \
                 : "=r"(r0), "=r"(r1), "=r"(r2), "=r"(r3) : "r"(addr))

#define MMA16832(c0, c1, c2, c3, a0, a1, a2, a3, b0, b1) \
    asm volatile("mma.sync.aligned.m16n8k32.row.col.s32.s8.s8.s32 " \
                 "{%0,%1,%2,%3},{%4,%5,%6,%7},{%8,%9},{%0,%1,%2,%3};" \
                 : "+r"(c0), "+r"(c1), "+r"(c2), "+r"(c3) \
                 : "r"(a0), "r"(a1), "r"(a2), "r"(a3), "r"(b0), "r"(b1))

// ---------------------------------------------------------------------------
// Kernel 1: clean + L2-normalize + int8 quantize. One warp per row.
// q = rint(x * 127 / maxabs);  g_scale = maxabs / (127 * max(norm, eps)).
// ---------------------------------------------------------------------------
__global__ __launch_bounds__(256) void normalize_kernel(
    const float* __restrict__ z1, const float* __restrict__ z2, float* __restrict__ out) {
    int w = threadIdx.x >> 5, lane = threadIdx.x & 31;
    int row = blockIdx.x * 8 + w;
    const float* src = (row < NS) ? (z1 + (size_t)row * DDIM)
                                  : (z2 + (size_t)(row - NS) * DDIM);
    float4 v0 = *(const float4*)(src + lane * 8);
    float4 v1 = *(const float4*)(src + lane * 8 + 4);
    float x[8] = {v0.x, v0.y, v0.z, v0.w, v1.x, v1.y, v1.z, v1.w};
    float ss = 0.0f, mx = 0.0f;
#pragma unroll
    for (int i = 0; i < 8; i++) {
        if (!isfinite(x[i])) x[i] = 0.0f;
        ss = fmaf(x[i], x[i], ss);
        mx = fmaxf(mx, fabsf(x[i]));
    }
#pragma unroll
    for (int off = 16; off; off >>= 1) {
        ss += __shfl_xor_sync(0xffffffffu, ss, off);
        mx = fmaxf(mx, __shfl_xor_sync(0xffffffffu, mx, off));
    }
    float qmul = (mx > 0.0f) ? 127.0f / mx : 0.0f;
    int q[8];
#pragma unroll
    for (int i = 0; i < 8; i++) q[i] = __float2int_rn(x[i] * qmul);
    uint32_t p0 = (uint32_t)(q[0] & 255) | ((uint32_t)(q[1] & 255) << 8) |
                  ((uint32_t)(q[2] & 255) << 16) | ((uint32_t)q[3] << 24);
    uint32_t p1 = (uint32_t)(q[4] & 255) | ((uint32_t)(q[5] & 255) << 8) |
                  ((uint32_t)(q[6] & 255) << 16) | ((uint32_t)q[7] << 24);
    *(uint2*)(g_feati + (size_t)row * 64 + lane * 2) = make_uint2(p0, p1);
    if (lane == 0) {
        g_scale[row] = mx / (127.0f * fmaxf(sqrtf(ss), 1e-12f));
        g_acc[row] = 0.0f;
        if (row == 0) out[0] = 0.0f;
    }
}

// ---------------------------------------------------------------------------
// Kernel 2: positive-pair dots via dp4a: pos[j] = dotint * sA * sB.
// ---------------------------------------------------------------------------
__global__ __launch_bounds__(256) void pos_kernel() {
    int w = threadIdx.x >> 5, lane = threadIdx.x & 31;
    int j = blockIdx.x * 8 + w;
    uint2 qa = *(const uint2*)(g_feati + (size_t)j * 64 + lane * 2);
    uint2 qb = *(const uint2*)(g_feati + (size_t)(j + NS) * 64 + lane * 2);
    int d = __dp4a((int)qa.x, (int)qb.x, __dp4a((int)qa.y, (int)qb.y, 0));
#pragma unroll
    for (int off = 16; off; off >>= 1)
        d += __shfl_xor_sync(0xffffffffu, d, off);
    if (lane == 0) g_pos[j] = (float)d * g_scale[j] * g_scale[j + NS];
}

// ---------------------------------------------------------------------------
// Kernel 3: fused IMMA sim GEMM + exp + row/col sums, upper triangle.
// 128x128 tile, 8 warps (4x2, warp tile 32x64). Whole K=256 (int8) loaded up
// front; 2 k-chunks of 128 B; XOR-swizzled 16 B segments (conflict-free
// ldmatrix.b16 on packed s8). Dequant by per-row scales in epilogue, then
// fixed-shift exp((s-1)/T); diag masked; col sums via symmetry.
// ---------------------------------------------------------------------------
struct FragI { int c[2][8][4]; };

__device__ __forceinline__ void load_tile(uint32_t dst0, const char* gbase, int t) {
#pragma unroll
    for (int o = 0; o < 8; o++) {
        int idx = t + o * 256;           // 0..2047 : 16B segments
        int r = idx >> 4;                // row 0..127
        int s = idx & 15;                // seg 0..15 (chunk = s>>3)
        int c = s >> 3, s7 = s & 7;
        CP16(dst0 + c * CHUNK_BYTES + r * 128 + ((s7 ^ (r & 7)) << 4),
             gbase + r * 256 + s * 16);
    }
}

__device__ __forceinline__ void compute_chunk(
    uint32_t sb, int chunk, int warp_m, int warp_n, int lane, FragI& f) {
    int lrow = lane & 15, khalf = lane >> 4;
    uint32_t abase = sb + (uint32_t)(chunk * CHUNK_BYTES);
    uint32_t bbase = abase + TILE_BYTES;
#pragma unroll
    for (int ks = 0; ks < 4; ks++) {
        int segk = 2 * ks + khalf;
        uint32_t a0[4], a1[4];
        {
            int r = warp_m * 32 + lrow;
            LDSM4(a0[0], a0[1], a0[2], a0[3], abase + r * 128 + ((segk ^ (r & 7)) << 4));
            r += 16;
            LDSM4(a1[0], a1[1], a1[2], a1[3], abase + r * 128 + ((segk ^ (r & 7)) << 4));
        }
#pragma unroll
        for (int jj = 0; jj < 4; jj++) {
            int r = warp_n * 64 + jj * 16 + lrow;
            uint32_t b0, b1, b2, b3;
            LDSM4(b0, b1, b2, b3, bbase + r * 128 + ((segk ^ (r & 7)) << 4));
            MMA16832(f.c[0][jj*2][0], f.c[0][jj*2][1], f.c[0][jj*2][2], f.c[0][jj*2][3],
                     a0[0], a0[1], a0[2], a0[3], b0, b2);
            MMA16832(f.c[0][jj*2+1][0], f.c[0][jj*2+1][1], f.c[0][jj*2+1][2], f.c[0][jj*2+1][3],
                     a0[0], a0[1], a0[2], a0[3], b1, b3);
            MMA16832(f.c[1][jj*2][0], f.c[1][jj*2][1], f.c[1][jj*2][2], f.c[1][jj*2][3],
                     a1[0], a1[1], a1[2], a1[3], b0, b2);
            MMA16832(f.c[1][jj*2+1][0], f.c[1][jj*2+1][1], f.c[1][jj*2+1][2], f.c[1][jj*2+1][3],
                     a1[0], a1[1], a1[2], a1[3], b1, b3);
        }
    }
}

__global__ __launch_bounds__(256, 2) void sim_kernel() {
    int bi = blockIdx.y, bj = blockIdx.x;
    if (bj < bi) return;     // lower triangle via symmetry

    extern __shared__ char smem[];
    __shared__ float sColScale[128];
    __shared__ float sRowScale[128];
    uint32_t sb = smem_u32(smem);
    int t = threadIdx.x, lane = t & 31, wid = t >> 5;
    int warp_m = wid & 3, warp_n = wid >> 2;

    const char* gA = (const char*)(g_feati + (size_t)bi * 128 * 64);
    const char* gB = (const char*)(g_feati + (size_t)bj * 128 * 64);

    // Chunk 0 of A+B first (so compute can start earliest), then chunk 1.
#pragma unroll
    for (int o = 0; o < 4; o++) {           // A chunk0 + B chunk0
        int idx = t + o * 256;              // 0..1023
        int r = idx >> 3, s7 = idx & 7;
        CP16(sb + r * 128 + ((s7 ^ (r & 7)) << 4), gA + r * 256 + s7 * 16);
    }
#pragma unroll
    for (int o = 0; o < 4; o++) {
        int idx = t + o * 256;
        int r = idx >> 3, s7 = idx & 7;
        CP16(sb + TILE_BYTES + r * 128 + ((s7 ^ (r & 7)) << 4), gB + r * 256 + s7 * 16);
    }
    CP_COMMIT();
#pragma unroll
    for (int o = 0; o < 4; o++) {           // A chunk1 + B chunk1
        int idx = t + o * 256;
        int r = idx >> 3, s7 = idx & 7;
        CP16(sb + CHUNK_BYTES + r * 128 + ((s7 ^ (r & 7)) << 4),
             gA + r * 256 + 128 + s7 * 16);
    }
#pragma unroll
    for (int o = 0; o < 4; o++) {
        int idx = t + o * 256;
        int r = idx >> 3, s7 = idx & 7;
        CP16(sb + TILE_BYTES + CHUNK_BYTES + r * 128 + ((s7 ^ (r & 7)) << 4),
             gB + r * 256 + 128 + s7 * 16);
    }
    CP_COMMIT();

    // Stage dequant scales (visible after the syncthreads below).
    if (t < 128) sColScale[t] = g_scale[bj * 128 + t];
    else         sRowScale[t - 128] = g_scale[bi * 128 + (t - 128)];

    FragI f;
#pragma unroll
    for (int i = 0; i < 2; i++)
#pragma unroll
        for (int j = 0; j < 8; j++)
#pragma unroll
            for (int k = 0; k < 4; k++) f.c[i][j][k] = 0;

    CP_WAIT(1); __syncthreads();
    compute_chunk(sb, 0, warp_m, warp_n, lane, f);
    CP_WAIT(0); __syncthreads();
    compute_chunk(sb, 1, warp_m, warp_n, lane, f);

    // ---- Epilogue: dequant + exp + row sums + (off-diag) col sums ----
    bool diag = (bi == bj);
    int r0 = lane >> 2;          // 0..7
    int cq = (lane & 3) * 2;     // 0,2,4,6
    float rowsum[2][2] = {{0.f, 0.f}, {0.f, 0.f}};
    float colsum[8][2];
#pragma unroll
    for (int j = 0; j < 8; j++) { colsum[j][0] = 0.f; colsum[j][1] = 0.f; }

    float sA[2][2];
#pragma unroll
    for (int i = 0; i < 2; i++) {
        sA[i][0] = sRowScale[warp_m * 32 + i * 16 + r0];
        sA[i][1] = sRowScale[warp_m * 32 + i * 16 + r0 + 8];
    }

#pragma unroll
    for (int j = 0; j < 8; j++) {
        float sB0 = sColScale[warp_n * 64 + j * 8 + cq];
        float sB1 = sColScale[warp_n * 64 + j * 8 + cq + 1];
        int gc = bj * 128 + warp_n * 64 + j * 8 + cq;
#pragma unroll
        for (int i = 0; i < 2; i++) {
            int grA = bi * 128 + warp_m * 32 + i * 16 + r0;
            float v0 = (float)f.c[i][j][0] * (sA[i][0] * sB0);
            float v1 = (float)f.c[i][j][1] * (sA[i][0] * sB1);
            float v2 = (float)f.c[i][j][2] * (sA[i][1] * sB0);
            float v3 = (float)f.c[i][j][3] * (sA[i][1] * sB1);
            float e0 = __expf(fmaf(v0, INV_T, -INV_T));
            float e1 = __expf(fmaf(v1, INV_T, -INV_T));
            float e2 = __expf(fmaf(v2, INV_T, -INV_T));
            float e3 = __expf(fmaf(v3, INV_T, -INV_T));
            if (diag) {
                if (grA == gc)         e0 = 0.0f;
                if (grA == gc + 1)     e1 = 0.0f;
                if (grA + 8 == gc)     e2 = 0.0f;
                if (grA + 8 == gc + 1) e3 = 0.0f;
            }
            rowsum[i][0] += e0 + e1;
            rowsum[i][1] += e2 + e3;
            colsum[j][0] += e0 + e2;
            colsum[j][1] += e1 + e3;
        }
    }

#pragma unroll
    for (int i = 0; i < 2; i++)
#pragma unroll
        for (int h = 0; h < 2; h++) {
            rowsum[i][h] += __shfl_xor_sync(0xffffffffu, rowsum[i][h], 1);
            rowsum[i][h] += __shfl_xor_sync(0xffffffffu, rowsum[i][h], 2);
        }
    if ((lane & 3) == 0) {
#pragma unroll
        for (int i = 0; i < 2; i++) {
            int gr = bi * 128 + warp_m * 32 + i * 16 + r0;
            atomicAdd(&g_acc[gr], rowsum[i][0]);
            atomicAdd(&g_acc[gr + 8], rowsum[i][1]);
        }
    }

    if (!diag) {
#pragma unroll
        for (int j = 0; j < 8; j++)
#pragma unroll
            for (int h = 0; h < 2; h++) {
                colsum[j][h] += __shfl_xor_sync(0xffffffffu, colsum[j][h], 4);
                colsum[j][h] += __shfl_xor_sync(0xffffffffu, colsum[j][h], 8);
                colsum[j][h] += __shfl_xor_sync(0xffffffffu, colsum[j][h], 16);
            }
        if (lane < 4) {
#pragma unroll
            for (int j = 0; j < 8; j++) {
                int gc = bj * 128 + warp_n * 64 + j * 8 + lane * 2;
                atomicAdd(&g_acc[gc], colsum[j][0]);
                atomicAdd(&g_acc[gc + 1], colsum[j][1]);
            }
        }
    }
}

// ---------------------------------------------------------------------------
// Kernel 4: loss = mean_i( 1/T + log(acc_i) - pos[i % NS] / T ).
// ---------------------------------------------------------------------------
__global__ __launch_bounds__(256) void final_kernel(float* __restrict__ out) {
    int t = threadIdx.x;
    int i = blockIdx.x * 256 + t;
    float s = INV_T + __logf(g_acc[i]) - g_pos[i & (NS - 1)] * INV_T;
#pragma unroll
    for (int off = 16; off; off >>= 1)
        s += __shfl_xor_sync(0xffffffffu, s, off);
    __shared__ float ws[8];
    int lane = t & 31, w = t >> 5;
    if (lane == 0) ws[w] = s;
    __syncthreads();
    if (t == 0) {
        float tot = 0.0f;
#pragma unroll
        for (int k = 0; k < 8; k++) tot += ws[k];
        atomicAdd(out, tot * (1.0f / (float)M_TOT));
    }
}

// ---------------------------------------------------------------------------
extern "C" void kernel_launch(void* const* d_in, const int* in_sizes, int n_in,
                              void* d_out, int out_size) {
    (void)in_sizes; (void)n_in; (void)out_size;
    const float* z1 = (const float*)d_in[0];
    const float* z2 = (const float*)d_in[1];
    float* out = (float*)d_out;

    cudaFuncSetAttribute(sim_kernel, cudaFuncAttributeMaxDynamicSharedMemorySize, SMEM_TOTAL);

    normalize_kernel<<<M_TOT / 8, 256>>>(z1, z2, out);
    pos_kernel<<<NS / 8, 256>>>();
    dim3 grid(64, 64);
    sim_kernel<<<grid, 256, SMEM_TOTAL>>>();
    final_kernel<<<M_TOT / 256, 256>>>(out);
}

// round 7
// speedup vs baseline: 1.4940x; 1.4940x over previous
#include <cuda_runtime.h>
#include <cuda_bf16.h>
#include <math.h>
#include <cstdint>

#define M_TOT 8192
#define NS    4096
#define DDIM  256
#define INV_T 14.285714285714286f    // 1 / 0.07
#define SH2   20.60992915555662f     // log2(e) / 0.07  (prefolded exp2 scale)

// sim kernel: 128x128 tile, K in 4 chunks of 64 (128 B/row), 3-stage cp.async ring
#define CHUNK_BYTES   (128 * 128)            // one tile-chunk: 128 rows x 128 B
#define STAGE_BYTES   (2 * CHUNK_BYTES)      // A chunk + B chunk
#define NUM_STAGES    3
#define SMEM_TOTAL    (NUM_STAGES * STAGE_BYTES)   // 98304 B

// Scratch (allocation-free rule: __device__ globals)
__device__ __align__(16) __nv_bfloat16 g_featb[M_TOT * DDIM];  // 4 MB
__device__ float g_acc[M_TOT];
__device__ float g_pos[NS];

// ---------------- helpers ----------------
__device__ __forceinline__ uint32_t smem_u32(const void* p) {
    uint32_t a;
    asm("{ .reg .u64 t; cvta.to.shared.u64 t, %1; cvt.u32.u64 %0, t; }" : "=r"(a) : "l"(p));
    return a;
}
#define CP16(dst, src) \
    asm volatile("cp.async.cg.shared.global [%0], [%1], 16;" :: "r"(dst), "l"(src))
#define CP_COMMIT() asm volatile("cp.async.commit_group;" ::: "memory")
#define CP_WAIT(n)  asm volatile("cp.async.wait_group %0;" :: "n"(n) : "memory")

#define LDSM4(r0, r1, r2, r3, addr) \
    asm volatile("ldmatrix.sync.aligned.m8n8.x4.shared.b16 {%0,%1,%2,%3}, [%4];" \
                 : "=r"(r0), "=r"(r1), "=r"(r2), "=r"(r3) : "r"(addr))

#define MMA16816(c0, c1, c2, c3, a0, a1, a2, a3, b0, b1) \
    asm volatile("mma.sync.aligned.m16n8k16.row.col.f32.bf16.bf16.f32 " \
                 "{%0,%1,%2,%3},{%4,%5,%6,%7},{%8,%9},{%0,%1,%2,%3};" \
                 : "+f"(c0), "+f"(c1), "+f"(c2), "+f"(c3) \
                 : "r"(a0), "r"(a1), "r"(a2), "r"(a3), "r"(b0), "r"(b1))

__device__ __forceinline__ float ex2(float x) {
    float r;
    asm("ex2.approx.ftz.f32 %0, %1;" : "=f"(r) : "f"(x));
    return r;
}

// ---------------------------------------------------------------------------
// Kernel 1: fused clean + L2-normalize + positive-pair dot.
// One warp per pair j: handles row j (from z1) and row j+NS (from z2).
// pos[j] = dot(x1,x2) / (max(|x1|,eps)*max(|x2|,eps))  computed in fp32.
// ---------------------------------------------------------------------------
__global__ __launch_bounds__(256) void normpos_kernel(
    const float* __restrict__ z1, const float* __restrict__ z2, float* __restrict__ out) {
    int w = threadIdx.x >> 5, lane = threadIdx.x & 31;
    int j = blockIdx.x * 8 + w;
    const float* s1 = z1 + (size_t)j * DDIM + lane * 8;
    const float* s2 = z2 + (size_t)j * DDIM + lane * 8;
    float4 a0 = *(const float4*)s1, a1 = *(const float4*)(s1 + 4);
    float4 b0 = *(const float4*)s2, b1 = *(const float4*)(s2 + 4);
    float x1[8] = {a0.x, a0.y, a0.z, a0.w, a1.x, a1.y, a1.z, a1.w};
    float x2[8] = {b0.x, b0.y, b0.z, b0.w, b1.x, b1.y, b1.z, b1.w};
    float ss1 = 0.f, ss2 = 0.f, sd = 0.f;
#pragma unroll
    for (int i = 0; i < 8; i++) {
        if (!isfinite(x1[i])) x1[i] = 0.0f;
        if (!isfinite(x2[i])) x2[i] = 0.0f;
        ss1 = fmaf(x1[i], x1[i], ss1);
        ss2 = fmaf(x2[i], x2[i], ss2);
        sd  = fmaf(x1[i], x2[i], sd);
    }
#pragma unroll
    for (int off = 16; off; off >>= 1) {
        ss1 += __shfl_xor_sync(0xffffffffu, ss1, off);
        ss2 += __shfl_xor_sync(0xffffffffu, ss2, off);
        sd  += __shfl_xor_sync(0xffffffffu, sd, off);
    }
    float inv1 = 1.0f / fmaxf(sqrtf(ss1), 1e-12f);
    float inv2 = 1.0f / fmaxf(sqrtf(ss2), 1e-12f);
    __nv_bfloat162 o[4];
#pragma unroll
    for (int i = 0; i < 4; i++)
        o[i] = __floats2bfloat162_rn(x1[2 * i] * inv1, x1[2 * i + 1] * inv1);
    *(uint2*)(g_featb + (size_t)j * DDIM + lane * 8) = *(uint2*)&o[0];
    *(uint2*)(g_featb + (size_t)j * DDIM + lane * 8 + 4) = *(uint2*)&o[2];
#pragma unroll
    for (int i = 0; i < 4; i++)
        o[i] = __floats2bfloat162_rn(x2[2 * i] * inv2, x2[2 * i + 1] * inv2);
    *(uint2*)(g_featb + (size_t)(j + NS) * DDIM + lane * 8) = *(uint2*)&o[0];
    *(uint2*)(g_featb + (size_t)(j + NS) * DDIM + lane * 8 + 4) = *(uint2*)&o[2];
    if (lane == 0) {
        g_pos[j] = sd * inv1 * inv2;
        g_acc[j] = 0.0f;
        g_acc[j + NS] = 0.0f;
        if (j == 0) out[0] = 0.0f;
    }
}

// ---------------------------------------------------------------------------
// Kernel 2: fused HMMA sim GEMM + exp + row/col sums, upper triangle.
// 1-D grid of exactly 2080 tiles; (bi,bj) decoded in-kernel. 128x128 CTA tile,
// 8 warps (4x2, warp tile 32x64). K=256 as 4 chunks of 64 cols; 3-stage
// cp.async ring (96 KB smem) -> 2 CTAs/SM. XOR-swizzled 16 B segments.
// ---------------------------------------------------------------------------
struct Frag { float c[2][8][4]; };

__device__ __forceinline__ void load_chunk(uint32_t sb, int st, int half,
                                           const char* gbase, int kc, int t) {
    uint32_t dst0 = sb + (uint32_t)(st * STAGE_BYTES + half * CHUNK_BYTES);
#pragma unroll
    for (int o = 0; o < 4; o++) {
        int idx = t + o * 256;           // 0..1023
        int r = idx >> 3, seg = idx & 7;
        CP16(dst0 + r * 128 + ((seg ^ (r & 7)) << 4),
             gbase + r * 512 + kc * 128 + seg * 16);
    }
}

__device__ __forceinline__ void compute_chunk(
    uint32_t sb, int st, int warp_m, int warp_n, int lane, Frag& f) {
    int lrow = lane & 15, khalf = lane >> 4;
    uint32_t abase = sb + (uint32_t)(st * STAGE_BYTES);
    uint32_t bbase = abase + CHUNK_BYTES;
#pragma unroll
    for (int ks = 0; ks < 4; ks++) {
        int segk = 2 * ks + khalf;
        uint32_t a0[4], a1[4];
        {
            int r = warp_m * 32 + lrow;
            LDSM4(a0[0], a0[1], a0[2], a0[3], abase + r * 128 + ((segk ^ (r & 7)) << 4));
            r += 16;
            LDSM4(a1[0], a1[1], a1[2], a1[3], abase + r * 128 + ((segk ^ (r & 7)) << 4));
        }
#pragma unroll
        for (int jj = 0; jj < 4; jj++) {
            int r = warp_n * 64 + jj * 16 + lrow;
            uint32_t b0, b1, b2, b3;
            LDSM4(b0, b1, b2, b3, bbase + r * 128 + ((segk ^ (r & 7)) << 4));
            MMA16816(f.c[0][jj*2][0], f.c[0][jj*2][1], f.c[0][jj*2][2], f.c[0][jj*2][3],
                     a0[0], a0[1], a0[2], a0[3], b0, b2);
            MMA16816(f.c[0][jj*2+1][0], f.c[0][jj*2+1][1], f.c[0][jj*2+1][2], f.c[0][jj*2+1][3],
                     a0[0], a0[1], a0[2], a0[3], b1, b3);
            MMA16816(f.c[1][jj*2][0], f.c[1][jj*2][1], f.c[1][jj*2][2], f.c[1][jj*2][3],
                     a1[0], a1[1], a1[2], a1[3], b0, b2);
            MMA16816(f.c[1][jj*2+1][0], f.c[1][jj*2+1][1], f.c[1][jj*2+1][2], f.c[1][jj*2+1][3],
                     a1[0], a1[1], a1[2], a1[3], b1, b3);
        }
    }
}

__global__ __launch_bounds__(256, 2) void sim_kernel() {
    // Decode upper-triangle tile (bi, bj) from linear block id.
    int q = blockIdx.x;
    int bi = (int)((129.0f - sqrtf(16641.0f - 8.0f * (float)q)) * 0.5f);
    while (64 * (bi + 1) - ((bi + 1) * bi) / 2 <= q) bi++;
    while (64 * bi - (bi * (bi - 1)) / 2 > q) bi--;
    int bj = bi + (q - (64 * bi - (bi * (bi - 1)) / 2));

    extern __shared__ char smem[];
    uint32_t sb = smem_u32(smem);
    int t = threadIdx.x, lane = t & 31, wid = t >> 5;
    int warp_m = wid & 3, warp_n = wid >> 2;

    const char* gA = (const char*)(g_featb + (size_t)bi * 128 * DDIM);
    const char* gB = (const char*)(g_featb + (size_t)bj * 128 * DDIM);

    // 3-stage pipeline over 4 K-chunks
    load_chunk(sb, 0, 0, gA, 0, t); load_chunk(sb, 0, 1, gB, 0, t); CP_COMMIT();
    load_chunk(sb, 1, 0, gA, 1, t); load_chunk(sb, 1, 1, gB, 1, t); CP_COMMIT();
    load_chunk(sb, 2, 0, gA, 2, t); load_chunk(sb, 2, 1, gB, 2, t); CP_COMMIT();

    Frag f;
#pragma unroll
    for (int i = 0; i < 2; i++)
#pragma unroll
        for (int j = 0; j < 8; j++)
#pragma unroll
            for (int k = 0; k < 4; k++) f.c[i][j][k] = 0.0f;

    CP_WAIT(2); __syncthreads();
    compute_chunk(sb, 0, warp_m, warp_n, lane, f);
    __syncthreads();
    load_chunk(sb, 0, 0, gA, 3, t); load_chunk(sb, 0, 1, gB, 3, t); CP_COMMIT();
    CP_WAIT(2); __syncthreads();
    compute_chunk(sb, 1, warp_m, warp_n, lane, f);
    CP_WAIT(1); __syncthreads();
    compute_chunk(sb, 2, warp_m, warp_n, lane, f);
    CP_WAIT(0); __syncthreads();
    compute_chunk(sb, 0, warp_m, warp_n, lane, f);

    // ---- Epilogue: exp2 + row sums + (off-diag) col sums ----
    bool diag = (bi == bj);
    int r0 = lane >> 2;          // 0..7
    int cq = (lane & 3) * 2;     // 0,2,4,6
    float rowsum[2][2] = {{0.f, 0.f}, {0.f, 0.f}};
    float colsum[8][2];
#pragma unroll
    for (int j = 0; j < 8; j++) { colsum[j][0] = 0.f; colsum[j][1] = 0.f; }

#pragma unroll
    for (int i = 0; i < 2; i++) {
        int grA = bi * 128 + warp_m * 32 + i * 16 + r0;
#pragma unroll
        for (int j = 0; j < 8; j++) {
            int gc = bj * 128 + warp_n * 64 + j * 8 + cq;
            float e0 = ex2(fmaf(f.c[i][j][0], SH2, -SH2));
            float e1 = ex2(fmaf(f.c[i][j][1], SH2, -SH2));
            float e2 = ex2(fmaf(f.c[i][j][2], SH2, -SH2));
            float e3 = ex2(fmaf(f.c[i][j][3], SH2, -SH2));
            if (diag) {
                if (grA == gc)         e0 = 0.0f;
                if (grA == gc + 1)     e1 = 0.0f;
                if (grA + 8 == gc)     e2 = 0.0f;
                if (grA + 8 == gc + 1) e3 = 0.0f;
            }
            rowsum[i][0] += e0 + e1;
            rowsum[i][1] += e2 + e3;
            colsum[j][0] += e0 + e2;
            colsum[j][1] += e1 + e3;
        }
    }

#pragma unroll
    for (int i = 0; i < 2; i++)
#pragma unroll
        for (int h = 0; h < 2; h++) {
            rowsum[i][h] += __shfl_xor_sync(0xffffffffu, rowsum[i][h], 1);
            rowsum[i][h] += __shfl_xor_sync(0xffffffffu, rowsum[i][h], 2);
        }
    if ((lane & 3) == 0) {
#pragma unroll
        for (int i = 0; i < 2; i++) {
            int gr = bi * 128 + warp_m * 32 + i * 16 + r0;
            atomicAdd(&g_acc[gr], rowsum[i][0]);
            atomicAdd(&g_acc[gr + 8], rowsum[i][1]);
        }
    }

    if (!diag) {
#pragma unroll
        for (int j = 0; j < 8; j++)
#pragma unroll
            for (int h = 0; h < 2; h++) {
                colsum[j][h] += __shfl_xor_sync(0xffffffffu, colsum[j][h], 4);
                colsum[j][h] += __shfl_xor_sync(0xffffffffu, colsum[j][h], 8);
                colsum[j][h] += __shfl_xor_sync(0xffffffffu, colsum[j][h], 16);
            }
        if (lane < 4) {
#pragma unroll
            for (int j = 0; j < 8; j++) {
                int gc = bj * 128 + warp_n * 64 + j * 8 + lane * 2;
                atomicAdd(&g_acc[gc], colsum[j][0]);
                atomicAdd(&g_acc[gc + 1], colsum[j][1]);
            }
        }
    }
}

// ---------------------------------------------------------------------------
// Kernel 3: loss = mean_i( 1/T + log(acc_i) - pos[i % NS] / T ).
// ---------------------------------------------------------------------------
__global__ __launch_bounds__(256) void final_kernel(float* __restrict__ out) {
    int t = threadIdx.x;
    int i = blockIdx.x * 256 + t;
    float s = INV_T + __logf(g_acc[i]) - g_pos[i & (NS - 1)] * INV_T;
#pragma unroll
    for (int off = 16; off; off >>= 1)
        s += __shfl_xor_sync(0xffffffffu, s, off);
    __shared__ float ws[8];
    int lane = t & 31, w = t >> 5;
    if (lane == 0) ws[w] = s;
    __syncthreads();
    if (t == 0) {
        float tot = 0.0f;
#pragma unroll
        for (int k = 0; k < 8; k++) tot += ws[k];
        atomicAdd(out, tot * (1.0f / (float)M_TOT));
    }
}

// ---------------------------------------------------------------------------
extern "C" void kernel_launch(void* const* d_in, const int* in_sizes, int n_in,
                              void* d_out, int out_size) {
    (void)in_sizes; (void)n_in; (void)out_size;
    const float* z1 = (const float*)d_in[0];
    const float* z2 = (const float*)d_in[1];
    float* out = (float*)d_out;

    cudaFuncSetAttribute(sim_kernel, cudaFuncAttributeMaxDynamicSharedMemorySize, SMEM_TOTAL);

    normpos_kernel<<<NS / 8, 256>>>(z1, z2, out);
    sim_kernel<<<2080, 256, SMEM_TOTAL>>>();
    final_kernel<<<M_TOT / 256, 256>>>(out);
}

// round 8
// speedup vs baseline: 2.1894x; 1.4654x over previous
#include <cuda_runtime.h>
#include <cuda_bf16.h>
#include <math.h>
#include <cstdint>

#define M_TOT 8192
#define NS    4096
#define DDIM  256
#define INV_T 14.285714285714286f    // 1 / 0.07
#define SH2   20.60992915555662f     // log2(e) / 0.07  (prefolded exp2 scale)

#define NTILE 64                      // 64 row-blocks of 128
#define NCTA  304                     // 2 per SM x 152 SMs (GB300)

// sim kernel: 128x128 tile, K in 4 chunks of 64 (128 B/row), 3-stage cp.async ring
#define CHUNK_BYTES   (128 * 128)            // one tile-chunk: 128 rows x 128 B
#define STAGE_BYTES   (2 * CHUNK_BYTES)      // A chunk + B chunk
#define SMEM_TOTAL    (3 * STAGE_BYTES)      // 98304 B

// Scratch (allocation-free rule: __device__ globals)
__device__ __align__(16) __nv_bfloat16 g_featb[M_TOT * DDIM];  // 4 MB
__device__ float g_acc[M_TOT];
__device__ float g_pos[NS];

// ---------------- helpers ----------------
__device__ __forceinline__ uint32_t smem_u32(const void* p) {
    uint32_t a;
    asm("{ .reg .u64 t; cvta.to.shared.u64 t, %1; cvt.u32.u64 %0, t; }" : "=r"(a) : "l"(p));
    return a;
}
#define CP16(dst, src) \
    asm volatile("cp.async.cg.shared.global [%0], [%1], 16;" :: "r"(dst), "l"(src))
#define CP_COMMIT() asm volatile("cp.async.commit_group;" ::: "memory")
#define CP_WAIT(n)  asm volatile("cp.async.wait_group %0;" :: "n"(n) : "memory")

#define LDSM4(r0, r1, r2, r3, addr) \
    asm volatile("ldmatrix.sync.aligned.m8n8.x4.shared.b16 {%0,%1,%2,%3}, [%4];" \
                 : "=r"(r0), "=r"(r1), "=r"(r2), "=r"(r3) : "r"(addr))

#define MMA16816(c0, c1, c2, c3, a0, a1, a2, a3, b0, b1) \
    asm volatile("mma.sync.aligned.m16n8k16.row.col.f32.bf16.bf16.f32 " \
                 "{%0,%1,%2,%3},{%4,%5,%6,%7},{%8,%9},{%0,%1,%2,%3};" \
                 : "+f"(c0), "+f"(c1), "+f"(c2), "+f"(c3) \
                 : "r"(a0), "r"(a1), "r"(a2), "r"(a3), "r"(b0), "r"(b1))

__device__ __forceinline__ float ex2(float x) {
    float r;
    asm("ex2.approx.ftz.f32 %0, %1;" : "=f"(r) : "f"(x));
    return r;
}

// ---------------------------------------------------------------------------
// Kernel 1: fused clean + L2-normalize + positive-pair dot (one warp per pair).
// ---------------------------------------------------------------------------
__global__ __launch_bounds__(256) void normpos_kernel(
    const float* __restrict__ z1, const float* __restrict__ z2, float* __restrict__ out) {
    int w = threadIdx.x >> 5, lane = threadIdx.x & 31;
    int j = blockIdx.x * 8 + w;
    const float* s1 = z1 + (size_t)j * DDIM + lane * 8;
    const float* s2 = z2 + (size_t)j * DDIM + lane * 8;
    float4 a0 = *(const float4*)s1, a1 = *(const float4*)(s1 + 4);
    float4 b0 = *(const float4*)s2, b1 = *(const float4*)(s2 + 4);
    float x1[8] = {a0.x, a0.y, a0.z, a0.w, a1.x, a1.y, a1.z, a1.w};
    float x2[8] = {b0.x, b0.y, b0.z, b0.w, b1.x, b1.y, b1.z, b1.w};
    float ss1 = 0.f, ss2 = 0.f, sd = 0.f;
#pragma unroll
    for (int i = 0; i < 8; i++) {
        if (!isfinite(x1[i])) x1[i] = 0.0f;
        if (!isfinite(x2[i])) x2[i] = 0.0f;
        ss1 = fmaf(x1[i], x1[i], ss1);
        ss2 = fmaf(x2[i], x2[i], ss2);
        sd  = fmaf(x1[i], x2[i], sd);
    }
#pragma unroll
    for (int off = 16; off; off >>= 1) {
        ss1 += __shfl_xor_sync(0xffffffffu, ss1, off);
        ss2 += __shfl_xor_sync(0xffffffffu, ss2, off);
        sd  += __shfl_xor_sync(0xffffffffu, sd, off);
    }
    float inv1 = 1.0f / fmaxf(sqrtf(ss1), 1e-12f);
    float inv2 = 1.0f / fmaxf(sqrtf(ss2), 1e-12f);
    __nv_bfloat162 o[4];
#pragma unroll
    for (int i = 0; i < 4; i++)
        o[i] = __floats2bfloat162_rn(x1[2 * i] * inv1, x1[2 * i + 1] * inv1);
    *(uint2*)(g_featb + (size_t)j * DDIM + lane * 8) = *(uint2*)&o[0];
    *(uint2*)(g_featb + (size_t)j * DDIM + lane * 8 + 4) = *(uint2*)&o[2];
#pragma unroll
    for (int i = 0; i < 4; i++)
        o[i] = __floats2bfloat162_rn(x2[2 * i] * inv2, x2[2 * i + 1] * inv2);
    *(uint2*)(g_featb + (size_t)(j + NS) * DDIM + lane * 8) = *(uint2*)&o[0];
    *(uint2*)(g_featb + (size_t)(j + NS) * DDIM + lane * 8 + 4) = *(uint2*)&o[2];
    if (lane == 0) {
        g_pos[j] = sd * inv1 * inv2;
        g_acc[j] = 0.0f;
        g_acc[j + NS] = 0.0f;
        if (j == 0) out[0] = 0.0f;
    }
}

// ---------------------------------------------------------------------------
// Kernel 2: persistent fused HMMA sim GEMM + exp + row/col sums (triangle).
// 304 persistent CTAs; each owns a contiguous run of tiles. All tiles' K-chunks
// form one continuous stream through a 3-stage cp.async ring: one wait+sync per
// chunk, prefetch depth 2, epilogue overlapped with next tile's loads.
// Mainloop/epilogue body identical to the proven round-5 kernel.
// ---------------------------------------------------------------------------
struct Frag { float c[2][8][4]; };

__device__ __forceinline__ void compute_chunk(
    uint32_t sb, int st, int warp_m, int warp_n, int lane, Frag& f) {
    int lrow = lane & 15, khalf = lane >> 4;
    uint32_t abase = sb + (uint32_t)(st * STAGE_BYTES);
    uint32_t bbase = abase + CHUNK_BYTES;
#pragma unroll
    for (int ks = 0; ks < 4; ks++) {
        int segk = 2 * ks + khalf;
        uint32_t a0[4], a1[4];
        {
            int r = warp_m * 32 + lrow;
            LDSM4(a0[0], a0[1], a0[2], a0[3], abase + r * 128 + ((segk ^ (r & 7)) << 4));
            r += 16;
            LDSM4(a1[0], a1[1], a1[2], a1[3], abase + r * 128 + ((segk ^ (r & 7)) << 4));
        }
#pragma unroll
        for (int jj = 0; jj < 4; jj++) {
            int r = warp_n * 64 + jj * 16 + lrow;
            uint32_t b0, b1, b2, b3;
            LDSM4(b0, b1, b2, b3, bbase + r * 128 + ((segk ^ (r & 7)) << 4));
            MMA16816(f.c[0][jj*2][0], f.c[0][jj*2][1], f.c[0][jj*2][2], f.c[0][jj*2][3],
                     a0[0], a0[1], a0[2], a0[3], b0, b2);
            MMA16816(f.c[0][jj*2+1][0], f.c[0][jj*2+1][1], f.c[0][jj*2+1][2], f.c[0][jj*2+1][3],
                     a0[0], a0[1], a0[2], a0[3], b1, b3);
            MMA16816(f.c[1][jj*2][0], f.c[1][jj*2][1], f.c[1][jj*2][2], f.c[1][jj*2][3],
                     a1[0], a1[1], a1[2], a1[3], b0, b2);
            MMA16816(f.c[1][jj*2+1][0], f.c[1][jj*2+1][1], f.c[1][jj*2+1][2], f.c[1][jj*2+1][3],
                     a1[0], a1[1], a1[2], a1[3], b1, b3);
        }
    }
}

__global__ __launch_bounds__(256, 2) void sim_kernel() {
    extern __shared__ char smem[];
    uint32_t sb = smem_u32(smem);
    int t = threadIdx.x, lane = t & 31, wid = t >> 5;
    int warp_m = wid & 3, warp_n = wid >> 2;
    int cta = blockIdx.x;

    // Contiguous tile range: first 256 CTAs get 7 tiles, rest get 6 (256*7+48*6=2080).
    int nt = 6 + (cta < 256 ? 1 : 0);
    int start = cta * 6 + (cta < 256 ? cta : 256);
    int C4 = nt * 4;

    // Decode start tile (bi, bj) by integer walk over triangle rows.
    int bi = 0, rem = start;
    while (rem >= NTILE - bi) { rem -= NTILE - bi; bi++; }
    int bj = bi + rem;

    // Per-thread load offsets (fixed): 4 x 16B segments per chunk-half.
    uint32_t doff[4]; int soff[4];
#pragma unroll
    for (int o = 0; o < 4; o++) {
        int idx = t + o * 256;
        int r = idx >> 3, seg = idx & 7;
        doff[o] = (uint32_t)(r * 128 + ((seg ^ (r & 7)) << 4));
        soff[o] = r * 512 + seg * 16;
    }

    const char* base = (const char*)g_featb;
    int lbi = bi, lbj = bj;                       // load-cursor tile
    const char* lgA = base + (size_t)lbi * 65536; // 128 rows * 512 B
    const char* lgB = base + (size_t)lbj * 65536;

    // Prologue: chunks 0 and 1 of the first tile.
#pragma unroll
    for (int o = 0; o < 4; o++) CP16(sb + doff[o], lgA + soff[o]);
#pragma unroll
    for (int o = 0; o < 4; o++) CP16(sb + CHUNK_BYTES + doff[o], lgB + soff[o]);
    CP_COMMIT();
#pragma unroll
    for (int o = 0; o < 4; o++) CP16(sb + STAGE_BYTES + doff[o], lgA + 128 + soff[o]);
#pragma unroll
    for (int o = 0; o < 4; o++) CP16(sb + STAGE_BYTES + CHUNK_BYTES + doff[o], lgB + 128 + soff[o]);
    CP_COMMIT();

    Frag f;
#pragma unroll
    for (int i = 0; i < 2; i++)
#pragma unroll
        for (int j = 0; j < 8; j++)
#pragma unroll
            for (int k = 0; k < 4; k++) f.c[i][j][k] = 0.0f;

    for (int c = 0; c < C4; c++) {
        if (c < C4 - 1) { CP_WAIT(1); } else { CP_WAIT(0); }
        __syncthreads();   // chunk c resident; all warps past compute(c-1)

        // Prefetch chunk c+2 into stage (c+2)%3 (freed by compute(c-1)).
        int pf = c + 2;
        if (pf < C4) {
            int kc = pf & 3;
            uint32_t d0 = sb + (uint32_t)((pf % 3) * STAGE_BYTES);
            const char* a = lgA + kc * 128;
            const char* b = lgB + kc * 128;
#pragma unroll
            for (int o = 0; o < 4; o++) CP16(d0 + doff[o], a + soff[o]);
#pragma unroll
            for (int o = 0; o < 4; o++) CP16(d0 + CHUNK_BYTES + doff[o], b + soff[o]);
            CP_COMMIT();
            if (kc == 3) {                      // load-cursor to next tile
                lbj++;
                if (lbj == NTILE) { lbi++; lbj = lbi; }
                lgA = base + (size_t)lbi * 65536;
                lgB = base + (size_t)lbj * 65536;
            }
        }

        compute_chunk(sb, c % 3, warp_m, warp_n, lane, f);

        if ((c & 3) == 3) {
            // ---- Epilogue for tile (bi, bj) ----
            bool diag = (bi == bj);
            int r0 = lane >> 2;
            int cq = (lane & 3) * 2;
            float rowsum[2][2] = {{0.f, 0.f}, {0.f, 0.f}};
            float colsum[8][2];
#pragma unroll
            for (int j = 0; j < 8; j++) { colsum[j][0] = 0.f; colsum[j][1] = 0.f; }

#pragma unroll
            for (int i = 0; i < 2; i++) {
                int grA = bi * 128 + warp_m * 32 + i * 16 + r0;
#pragma unroll
                for (int j = 0; j < 8; j++) {
                    int gc = bj * 128 + warp_n * 64 + j * 8 + cq;
                    float e0 = ex2(fmaf(f.c[i][j][0], SH2, -SH2));
                    float e1 = ex2(fmaf(f.c[i][j][1], SH2, -SH2));
                    float e2 = ex2(fmaf(f.c[i][j][2], SH2, -SH2));
                    float e3 = ex2(fmaf(f.c[i][j][3], SH2, -SH2));
                    if (diag) {
                        if (grA == gc)         e0 = 0.0f;
                        if (grA == gc + 1)     e1 = 0.0f;
                        if (grA + 8 == gc)     e2 = 0.0f;
                        if (grA + 8 == gc + 1) e3 = 0.0f;
                    }
                    rowsum[i][0] += e0 + e1;
                    rowsum[i][1] += e2 + e3;
                    colsum[j][0] += e0 + e2;
                    colsum[j][1] += e1 + e3;
                }
            }

#pragma unroll
            for (int i = 0; i < 2; i++)
#pragma unroll
                for (int h = 0; h < 2; h++) {
                    rowsum[i][h] += __shfl_xor_sync(0xffffffffu, rowsum[i][h], 1);
                    rowsum[i][h] += __shfl_xor_sync(0xffffffffu, rowsum[i][h], 2);
                }
            if ((lane & 3) == 0) {
#pragma unroll
                for (int i = 0; i < 2; i++) {
                    int gr = bi * 128 + warp_m * 32 + i * 16 + r0;
                    atomicAdd(&g_acc[gr], rowsum[i][0]);
                    atomicAdd(&g_acc[gr + 8], rowsum[i][1]);
                }
            }
            if (!diag) {
#pragma unroll
                for (int j = 0; j < 8; j++)
#pragma unroll
                    for (int h = 0; h < 2; h++) {
                        colsum[j][h] += __shfl_xor_sync(0xffffffffu, colsum[j][h], 4);
                        colsum[j][h] += __shfl_xor_sync(0xffffffffu, colsum[j][h], 8);
                        colsum[j][h] += __shfl_xor_sync(0xffffffffu, colsum[j][h], 16);
                    }
                if (lane < 4) {
#pragma unroll
                    for (int j = 0; j < 8; j++) {
                        int gc = bj * 128 + warp_n * 64 + j * 8 + lane * 2;
                        atomicAdd(&g_acc[gc], colsum[j][0]);
                        atomicAdd(&g_acc[gc + 1], colsum[j][1]);
                    }
                }
            }
            // advance compute cursor + reset accumulators
            bj++;
            if (bj == NTILE) { bi++; bj = bi; }
#pragma unroll
            for (int i = 0; i < 2; i++)
#pragma unroll
                for (int j = 0; j < 8; j++)
#pragma unroll
                    for (int k = 0; k < 4; k++) f.c[i][j][k] = 0.0f;
        }
    }
}

// ---------------------------------------------------------------------------
// Kernel 3: loss = mean_i( 1/T + log(acc_i) - pos[i % NS] / T ).
// ---------------------------------------------------------------------------
__global__ __launch_bounds__(256) void final_kernel(float* __restrict__ out) {
    int t = threadIdx.x;
    int i = blockIdx.x * 256 + t;
    float s = INV_T + __logf(g_acc[i]) - g_pos[i & (NS - 1)] * INV_T;
#pragma unroll
    for (int off = 16; off; off >>= 1)
        s += __shfl_xor_sync(0xffffffffu, s, off);
    __shared__ float ws[8];
    int lane = t & 31, w = t >> 5;
    if (lane == 0) ws[w] = s;
    __syncthreads();
    if (t == 0) {
        float tot = 0.0f;
#pragma unroll
        for (int k = 0; k < 8; k++) tot += ws[k];
        atomicAdd(out, tot * (1.0f / (float)M_TOT));
    }
}

// ---------------------------------------------------------------------------
extern "C" void kernel_launch(void* const* d_in, const int* in_sizes, int n_in,
                              void* d_out, int out_size) {
    (void)in_sizes; (void)n_in; (void)out_size;
    const float* z1 = (const float*)d_in[0];
    const float* z2 = (const float*)d_in[1];
    float* out = (float*)d_out;

    cudaFuncSetAttribute(sim_kernel, cudaFuncAttributeMaxDynamicSharedMemorySize, SMEM_TOTAL);

    normpos_kernel<<<NS / 8, 256>>>(z1, z2, out);
    sim_kernel<<<NCTA, 256, SMEM_TOTAL>>>();
    final_kernel<<<M_TOT / 256, 256>>>(out);
}